// round 1
// baseline (speedup 1.0000x reference)
#include <cuda_runtime.h>
#include <cstdint>
#include <math.h>

#define B_SLIDES 64
#define N_CELLS  20000
#define NI       64
#define H1       16
#define H2       8
#define N_OUT    2

#define THREADS  256
#define CPT      8
#define CELLS_PER_BLOCK (THREADS * CPT)                                  // 2048
#define CHUNKS   ((N_CELLS + CELLS_PER_BLOCK - 1) / CELLS_PER_BLOCK)     // 10

// Partial sums per (slide, chunk): [sum_w, sum_w*h2[0..7]]
__device__ float g_partials[B_SLIDES * CHUNKS * 9];

typedef unsigned long long ull;

__device__ __forceinline__ ull pack2(float lo, float hi) {
    ull r; asm("mov.b64 %0, {%1, %2};" : "=l"(r) : "f"(lo), "f"(hi)); return r;
}
__device__ __forceinline__ void unpack2(ull v, float& lo, float& hi) {
    asm("mov.b64 {%0, %1}, %2;" : "=f"(lo), "=f"(hi) : "l"(v));
}
// Packed fp32x2 FMA (sm_100+): one instruction computes two fp32 FMAs.
__device__ __forceinline__ ull fma2(ull a, ull b, ull c) {
    ull d; asm("fma.rn.f32x2 %0, %1, %2, %3;" : "=l"(d) : "l"(a), "l"(b), "l"(c)); return d;
}

// One k-step of layer 1 for 4 cells (2 packed pairs): 16 outputs each.
__device__ __forceinline__ void l1_step(const ull* __restrict__ wrow,
                                        float xa, float xb, float xc, float xd,
                                        ull* acc01, ull* acc23) {
    ull p01 = pack2(xa, xb);
    ull p23 = pack2(xc, xd);
    #pragma unroll
    for (int j = 0; j < H1; ++j) {
        ull w = wrow[j];                 // LDS.64, broadcast (all lanes same addr)
        acc01[j] = fma2(p01, w, acc01[j]);
        acc23[j] = fma2(p23, w, acc23[j]);
    }
}

__global__ __launch_bounds__(THREADS) void mlp_pool_kernel(
    const float* __restrict__ X,
    const float* __restrict__ W1, const float* __restrict__ b1,
    const float* __restrict__ W2, const float* __restrict__ b2,
    const float* __restrict__ Ww, const float* __restrict__ bw)
{
    __shared__ float2 w1d[NI * H1];      // W1 duplicated into both packed halves
    __shared__ float  w2s[H1 * H2];
    __shared__ float  b1s[H1], b2s[H2], wws[H2];
    __shared__ float  bw_s;
    __shared__ float  red[9][THREADS / 32];

    const int tid   = threadIdx.x;
    const int b     = blockIdx.y;
    const int chunk = blockIdx.x;

    for (int k = tid; k < NI * H1; k += THREADS) { float v = W1[k]; w1d[k] = make_float2(v, v); }
    for (int k = tid; k < H1 * H2; k += THREADS) w2s[k] = W2[k];
    if (tid < H1) b1s[tid] = b1[tid];
    if (tid < H2) { b2s[tid] = b2[tid]; wws[tid] = Ww[tid]; }
    if (tid == 0) bw_s = bw[0];
    __syncthreads();

    const float* Xb    = X + (size_t)b * N_CELLS * NI;
    const int    nBase = chunk * CELLS_PER_BLOCK;

    float sw = 0.f;
    float swh[H2];
    #pragma unroll
    for (int j = 0; j < H2; ++j) swh[j] = 0.f;

    for (int g = 0; g < CPT; g += 4) {
        const int n0 = nBase + (g + 0) * THREADS + tid;
        const int n1 = nBase + (g + 1) * THREADS + tid;
        const int n2 = nBase + (g + 2) * THREADS + tid;
        const int n3 = nBase + (g + 3) * THREADS + tid;
        const bool vld[4] = { n0 < N_CELLS, n1 < N_CELLS, n2 < N_CELLS, n3 < N_CELLS };

        const float4* x0 = (const float4*)(Xb + (size_t)n0 * NI);
        const float4* x1 = (const float4*)(Xb + (size_t)n1 * NI);
        const float4* x2 = (const float4*)(Xb + (size_t)n2 * NI);
        const float4* x3 = (const float4*)(Xb + (size_t)n3 * NI);

        // ---- layer 1: [4 cells, 64] x [64, 16], packed 2 cells per fp32x2 lane ----
        ull acc01[H1], acc23[H1];
        #pragma unroll
        for (int j = 0; j < H1; ++j) {
            float bj = b1s[j];
            acc01[j] = pack2(bj, bj);
            acc23[j] = acc01[j];
        }

        const ull* wbase = (const ull*)w1d;
        const float4 z4 = make_float4(0.f, 0.f, 0.f, 0.f);

        #pragma unroll 4
        for (int i0 = 0; i0 < NI / 4; ++i0) {
            float4 a = vld[0] ? x0[i0] : z4;
            float4 c = vld[1] ? x1[i0] : z4;
            float4 d = vld[2] ? x2[i0] : z4;
            float4 e = vld[3] ? x3[i0] : z4;
            l1_step(wbase + (i0 * 4 + 0) * H1, a.x, c.x, d.x, e.x, acc01, acc23);
            l1_step(wbase + (i0 * 4 + 1) * H1, a.y, c.y, d.y, e.y, acc01, acc23);
            l1_step(wbase + (i0 * 4 + 2) * H1, a.z, c.z, d.z, e.z, acc01, acc23);
            l1_step(wbase + (i0 * 4 + 3) * H1, a.w, c.w, d.w, e.w, acc01, acc23);
        }

        // ---- per-cell tail: relu -> layer2 -> relu -> gate -> accumulate ----
        #pragma unroll
        for (int m = 0; m < 4; ++m) {
            float h1v[H1];
            #pragma unroll
            for (int j = 0; j < H1; ++j) {
                float lo, hi;
                unpack2((m < 2) ? acc01[j] : acc23[j], lo, hi);
                h1v[j] = fmaxf((m & 1) ? hi : lo, 0.f);
            }

            float h2v[H2];
            #pragma unroll
            for (int j2 = 0; j2 < H2; ++j2) {
                float s = b2s[j2];
                #pragma unroll
                for (int i = 0; i < H1; ++i) s += h1v[i] * w2s[i * H2 + j2];
                h2v[j2] = fmaxf(s, 0.f);
            }

            float zg = bw_s;
            #pragma unroll
            for (int i = 0; i < H2; ++i) zg += h2v[i] * wws[i];
            float wgt = 1.f / (1.f + expf(-zg));
            if (!vld[m]) wgt = 0.f;

            sw += wgt;
            #pragma unroll
            for (int j = 0; j < H2; ++j) swh[j] += wgt * h2v[j];
        }
    }

    // ---- block reduction (deterministic: fixed tree) ----
    float vals[9];
    vals[0] = sw;
    #pragma unroll
    for (int j = 0; j < H2; ++j) vals[j + 1] = swh[j];

    #pragma unroll
    for (int off = 16; off > 0; off >>= 1) {
        #pragma unroll
        for (int k = 0; k < 9; ++k)
            vals[k] += __shfl_down_sync(0xffffffffu, vals[k], off);
    }
    const int lane = tid & 31, warp = tid >> 5;
    if (lane == 0) {
        #pragma unroll
        for (int k = 0; k < 9; ++k) red[k][warp] = vals[k];
    }
    __syncthreads();
    if (tid < 9) {
        float s = 0.f;
        #pragma unroll
        for (int w = 0; w < THREADS / 32; ++w) s += red[tid][w];
        g_partials[((size_t)b * CHUNKS + chunk) * 9 + tid] = s;
    }
}

__global__ void finalize_kernel(const float* __restrict__ W4,
                                const float* __restrict__ b4,
                                float* __restrict__ out)
{
    int b = threadIdx.x;
    if (b >= B_SLIDES) return;
    float s[9];
    #pragma unroll
    for (int k = 0; k < 9; ++k) s[k] = 0.f;
    for (int c = 0; c < CHUNKS; ++c) {
        const float* p = g_partials + ((size_t)b * CHUNKS + c) * 9;
        #pragma unroll
        for (int k = 0; k < 9; ++k) s[k] += p[k];
    }
    float inv = 1.f / s[0];
    #pragma unroll
    for (int o = 0; o < N_OUT; ++o) {
        float r = b4[o];
        #pragma unroll
        for (int k = 0; k < H2; ++k) r += (s[k + 1] * inv) * W4[k * N_OUT + o];
        out[b * N_OUT + o] = r;
    }
}

extern "C" void kernel_launch(void* const* d_in, const int* in_sizes, int n_in,
                              void* d_out, int out_size)
{
    (void)in_sizes; (void)n_in; (void)out_size;
    const float* X  = (const float*)d_in[0];
    const float* W1 = (const float*)d_in[1];
    const float* b1 = (const float*)d_in[2];
    const float* W2 = (const float*)d_in[3];
    const float* b2 = (const float*)d_in[4];
    const float* Ww = (const float*)d_in[5];
    const float* bw = (const float*)d_in[6];
    const float* W4 = (const float*)d_in[7];
    const float* b4 = (const float*)d_in[8];

    dim3 grid(CHUNKS, B_SLIDES);
    mlp_pool_kernel<<<grid, THREADS>>>(X, W1, b1, W2, b2, Ww, bw);
    finalize_kernel<<<1, 64>>>(W4, b4, (float*)d_out);
}

// round 2
// speedup vs baseline: 1.6332x; 1.6332x over previous
#include <cuda_runtime.h>
#include <cstdint>
#include <math.h>

#define B_SLIDES 64
#define N_CELLS  20000
#define NI       64
#define H1       16
#define H2       8
#define N_OUT    2

#define TPB      128               // threads per block = cells per stage
#define ROW      68                // padded floats per SMEM row (conflict-free)
#define CHUNKS   13                // grid.x; 13*64 = 832 blocks ~= one wave
#define CELLS_PER_CHUNK ((N_CELLS + CHUNKS - 1) / CHUNKS)   // 1539

typedef unsigned long long ull;

// ---- constant-memory weights (raw copies; adjacent j form fp32 pairs) ----
__constant__ ull   cW1p[NI * H1 / 2];   // W1[64][16] as [64][8] pairs (4KB)
__constant__ ull   cW2p[H1 * H2 / 2];   // W2[16][8]  as [16][4] pairs
__constant__ float cb1[H1];
__constant__ float cb2[H2];
__constant__ ull   cWwp[H2 / 2];        // Ww[8] as 4 pairs
__constant__ float cbw[1];

// Partial sums per (slide, chunk): [sum_w, sum_w*h2[0..7]]
__device__ float g_partials[B_SLIDES * CHUNKS * 9];

__device__ __forceinline__ ull pack2(float lo, float hi) {
    ull r; asm("mov.b64 %0, {%1, %2};" : "=l"(r) : "f"(lo), "f"(hi)); return r;
}
__device__ __forceinline__ void unpack2(ull v, float& lo, float& hi) {
    asm("mov.b64 {%0, %1}, %2;" : "=f"(lo), "=f"(hi) : "l"(v));
}
// Packed fp32x2 FMA (sm_100+): two fp32 FMAs in one instruction.
__device__ __forceinline__ ull fma2(ull a, ull b, ull c) {
    ull d; asm("fma.rn.f32x2 %0, %1, %2, %3;" : "=l"(d) : "l"(a), "l"(b), "l"(c)); return d;
}

__global__ __launch_bounds__(TPB) void mlp_pool_kernel(const float* __restrict__ X)
{
    __shared__ float xs[TPB * ROW];          // 34816 B staging buffer
    __shared__ float red[9][TPB / 32];

    const int tid   = threadIdx.x;
    const int b     = blockIdx.y;
    const int chunk = blockIdx.x;

    const int start = chunk * CELLS_PER_CHUNK;
    const int end   = min(start + CELLS_PER_CHUNK, N_CELLS);

    const float4* __restrict__ Xg =
        (const float4*)(X + (size_t)b * N_CELLS * NI);

    float sw = 0.f;
    ull swh[4];
    #pragma unroll
    for (int k = 0; k < 4; ++k) swh[k] = pack2(0.f, 0.f);

    for (int base = start; base < end; base += TPB) {
        __syncthreads();                      // buffer reuse guard
        const int nvalid = end - base;

        // ---- coalesced stage: 128 cells x 64 floats -> padded SMEM ----
        #pragma unroll
        for (int k = 0; k < 16; ++k) {
            int f = tid + k * TPB;            // 0..2047, contiguous across warp
            int c = f >> 4;                   // cell row 0..127
            int o = f & 15;                   // float4 offset in row
            float4 v = make_float4(0.f, 0.f, 0.f, 0.f);
            if (c < nvalid) v = Xg[(size_t)(base + c) * (NI / 4) + o];
            *(float4*)&xs[c * ROW + o * 4] = v;
        }
        __syncthreads();

        const bool valid = (tid < nvalid);

        // ---- layer 1: 64 -> 16, outputs packed as 8 fp32x2 accumulators ----
        ull acc[8];
        #pragma unroll
        for (int jp = 0; jp < 8; ++jp) acc[jp] = pack2(cb1[2 * jp], cb1[2 * jp + 1]);

        const float4* xrow = (const float4*)&xs[tid * ROW];
        #pragma unroll
        for (int i4 = 0; i4 < 16; ++i4) {
            float4 xv = xrow[i4];             // conflict-free LDS.128
            #pragma unroll
            for (int s = 0; s < 4; ++s) {
                int i = i4 * 4 + s;
                float xc = (s == 0) ? xv.x : (s == 1) ? xv.y : (s == 2) ? xv.z : xv.w;
                ull x2 = pack2(xc, xc);
                const ulonglong2* wrow = (const ulonglong2*)&cW1p[i * 8]; // ULDC.128
                #pragma unroll
                for (int jq = 0; jq < 4; ++jq) {
                    ulonglong2 w = wrow[jq];
                    acc[2 * jq + 0] = fma2(x2, w.x, acc[2 * jq + 0]);
                    acc[2 * jq + 1] = fma2(x2, w.y, acc[2 * jq + 1]);
                }
            }
        }

        float h1[H1];
        #pragma unroll
        for (int jp = 0; jp < 8; ++jp) {
            float lo, hi; unpack2(acc[jp], lo, hi);
            h1[2 * jp]     = fmaxf(lo, 0.f);
            h1[2 * jp + 1] = fmaxf(hi, 0.f);
        }

        // ---- layer 2: 16 -> 8, packed ----
        ull acc2[4];
        #pragma unroll
        for (int kp = 0; kp < 4; ++kp) acc2[kp] = pack2(cb2[2 * kp], cb2[2 * kp + 1]);
        const ulonglong2* w2p = (const ulonglong2*)cW2p;   // [16][2] of ull2
        #pragma unroll
        for (int i = 0; i < H1; ++i) {
            ull h2x = pack2(h1[i], h1[i]);
            ulonglong2 wa = w2p[i * 2 + 0];
            ulonglong2 wb = w2p[i * 2 + 1];
            acc2[0] = fma2(h2x, wa.x, acc2[0]);
            acc2[1] = fma2(h2x, wa.y, acc2[1]);
            acc2[2] = fma2(h2x, wb.x, acc2[2]);
            acc2[3] = fma2(h2x, wb.y, acc2[3]);
        }

        float h2[H2];
        #pragma unroll
        for (int kp = 0; kp < 4; ++kp) {
            float lo, hi; unpack2(acc2[kp], lo, hi);
            h2[2 * kp]     = fmaxf(lo, 0.f);
            h2[2 * kp + 1] = fmaxf(hi, 0.f);
        }

        // ---- sigmoid gate ----
        ull g = pack2(cbw[0], 0.f);
        #pragma unroll
        for (int kp = 0; kp < 4; ++kp)
            g = fma2(pack2(h2[2 * kp], h2[2 * kp + 1]), cWwp[kp], g);
        float glo, ghi; unpack2(g, glo, ghi);
        float zg  = glo + ghi;
        float wgt = 1.f / (1.f + __expf(-zg));

        if (valid) {
            sw += wgt;
            ull wp = pack2(wgt, wgt);
            #pragma unroll
            for (int kp = 0; kp < 4; ++kp)
                swh[kp] = fma2(wp, pack2(h2[2 * kp], h2[2 * kp + 1]), swh[kp]);
        }
    }

    // ---- deterministic block reduction of 9 values ----
    float vals[9];
    vals[0] = sw;
    #pragma unroll
    for (int kp = 0; kp < 4; ++kp) {
        float lo, hi; unpack2(swh[kp], lo, hi);
        vals[1 + 2 * kp] = lo; vals[2 + 2 * kp] = hi;
    }
    #pragma unroll
    for (int off = 16; off > 0; off >>= 1) {
        #pragma unroll
        for (int k = 0; k < 9; ++k)
            vals[k] += __shfl_down_sync(0xffffffffu, vals[k], off);
    }
    const int lane = tid & 31, warp = tid >> 5;
    if (lane == 0) {
        #pragma unroll
        for (int k = 0; k < 9; ++k) red[k][warp] = vals[k];
    }
    __syncthreads();
    if (tid < 9) {
        float s = 0.f;
        #pragma unroll
        for (int w = 0; w < TPB / 32; ++w) s += red[tid][w];
        g_partials[((size_t)b * CHUNKS + chunk) * 9 + tid] = s;
    }
}

__global__ void finalize_kernel(const float* __restrict__ W4,
                                const float* __restrict__ b4,
                                float* __restrict__ out)
{
    int b = threadIdx.x;
    if (b >= B_SLIDES) return;
    float s[9];
    #pragma unroll
    for (int k = 0; k < 9; ++k) s[k] = 0.f;
    for (int c = 0; c < CHUNKS; ++c) {
        const float* p = g_partials + ((size_t)b * CHUNKS + c) * 9;
        #pragma unroll
        for (int k = 0; k < 9; ++k) s[k] += p[k];
    }
    float inv = 1.f / s[0];
    #pragma unroll
    for (int o = 0; o < N_OUT; ++o) {
        float r = b4[o];
        #pragma unroll
        for (int k = 0; k < H2; ++k) r += (s[k + 1] * inv) * W4[k * N_OUT + o];
        out[b * N_OUT + o] = r;
    }
}

extern "C" void kernel_launch(void* const* d_in, const int* in_sizes, int n_in,
                              void* d_out, int out_size)
{
    (void)in_sizes; (void)n_in; (void)out_size;
    const float* X  = (const float*)d_in[0];

    // Raw byte copies into constant memory (D2D, graph-capturable).
    cudaMemcpyToSymbolAsync(cW1p, d_in[1], NI * H1 * sizeof(float), 0,
                            cudaMemcpyDeviceToDevice, 0);
    cudaMemcpyToSymbolAsync(cb1,  d_in[2], H1 * sizeof(float), 0,
                            cudaMemcpyDeviceToDevice, 0);
    cudaMemcpyToSymbolAsync(cW2p, d_in[3], H1 * H2 * sizeof(float), 0,
                            cudaMemcpyDeviceToDevice, 0);
    cudaMemcpyToSymbolAsync(cb2,  d_in[4], H2 * sizeof(float), 0,
                            cudaMemcpyDeviceToDevice, 0);
    cudaMemcpyToSymbolAsync(cWwp, d_in[5], H2 * sizeof(float), 0,
                            cudaMemcpyDeviceToDevice, 0);
    cudaMemcpyToSymbolAsync(cbw,  d_in[6], sizeof(float), 0,
                            cudaMemcpyDeviceToDevice, 0);

    dim3 grid(CHUNKS, B_SLIDES);
    mlp_pool_kernel<<<grid, TPB>>>(X);
    finalize_kernel<<<1, 64>>>((const float*)d_in[7], (const float*)d_in[8],
                               (float*)d_out);
}